// round 7
// baseline (speedup 1.0000x reference)
#include <cuda_runtime.h>
#include <cstdint>

#define B_  8
#define T_  4096
#define DI  256
#define DO  256
#define M_TOTAL (B_ * T_)      // 32768

#define NCH   64               // chunks per sequence
#define CHUNK (T_ / NCH)       // 64 steps per chunk

// Scratch: interleaved (a, b) = (1-f, f*x) pairs, [M_TOTAL][DO] float2 = 64 MB
__device__ float g_ab[(size_t)M_TOTAL * DO * 2];
// Per-(b, chunk, o) carry composition and resolved chunk-entry state
__device__ float g_cA[B_ * NCH * DO];
__device__ float g_cS[B_ * NCH * DO];
__device__ float g_hin[B_ * NCH * DO];

__device__ __forceinline__ uint32_t f2tf32(float x) {
    uint32_t r;
    asm("cvt.rna.tf32.f32 %0, %1;" : "=r"(r) : "f"(x));
    return r;
}

__device__ __forceinline__ void cp16(float* dst, const float* src) {
    uint32_t d = (uint32_t)__cvta_generic_to_shared(dst);
    asm volatile("cp.async.cg.shared.global [%0], [%1], 16;\n" :: "r"(d), "l"(src));
}
#define CP_COMMIT()  asm volatile("cp.async.commit_group;\n" ::: "memory")
#define CP_WAIT(N)   asm volatile("cp.async.wait_group %0;\n" :: "n"(N) : "memory")

#define KC        32
#define SSTRIDE   36   // 32 + 4 pad: bank = 4*(lane/4)+lane%4 -> conflict-free
#define A_STG     (128 * SSTRIDE)       // floats per A stage
#define W_STG     (2 * 64 * SSTRIDE)    // floats per W stage (both matrices)
#define SMEM_FLOATS (2 * (A_STG + W_STG))   // 18432 floats = 72 KB

#define MMA_TF32(d, a, b0, b1)                                            \
    asm volatile(                                                         \
        "mma.sync.aligned.m16n8k8.row.col.f32.tf32.tf32.f32 "            \
        "{%0,%1,%2,%3}, {%4,%5,%6,%7}, {%8,%9}, {%0,%1,%2,%3};"          \
        : "+f"((d)[0]), "+f"((d)[1]), "+f"((d)[2]), "+f"((d)[3])          \
        : "r"((a)[0]), "r"((a)[1]), "r"((a)[2]), "r"((a)[3]),             \
          "r"(b0), "r"(b1))

// CTA: 256 threads, tile M=128 x O=64, computes BOTH projections.
// Grid: (DO/64, M_TOTAL/128) = (4, 256). cp.async 2-stage pipeline.
__global__ __launch_bounds__(256, 2) void qrnn_gemm(
    const float* __restrict__ in,    // [M_TOTAL, DI]
    const float* __restrict__ mask,  // [M_TOTAL]
    const float* __restrict__ Wx,    // [DO, DI]
    const float* __restrict__ bx,    // [DO]
    const float* __restrict__ Wf,    // [DO, DI]
    const float* __restrict__ bf)    // [DO]
{
    extern __shared__ float smem[];
    float* sA = smem;                 // [2][128*SSTRIDE]
    float* sW = smem + 2 * A_STG;     // [2][2][64*SSTRIDE]

    const int tid   = threadIdx.x;
    const int lane  = tid & 31;
    const int warp  = tid >> 5;
    const int warpM = warp & 3;      // 4 warps along M (32 rows each)
    const int warpN = warp >> 2;     // 2 warps along O (32 cols each)
    const int gid   = lane >> 2;     // 0..7
    const int tig   = lane & 3;      // 0..3

    const int m0 = blockIdx.y * 128;
    const int o0 = blockIdx.x * 64;

    // Per-thread staging coordinates (fixed across chunks)
    const int ar  = tid >> 3;               // A row group base (4 rows per thread via +32)
    const int ac4 = (tid & 7) << 2;         // A col (float4)
    const int wsel = tid >> 9;              // always 0 for tid<512; W uses lin split below

    float accx[2][4][4];
    float accf[2][4][4];
#pragma unroll
    for (int mf = 0; mf < 2; mf++)
#pragma unroll
        for (int nf = 0; nf < 4; nf++)
#pragma unroll
            for (int c = 0; c < 4; c++) { accx[mf][nf][c] = 0.f; accf[mf][nf][c] = 0.f; }
    (void)wsel; (void)ar; (void)ac4;

    // ---- async-copy issue for one K-chunk into stage s ----
    auto issue = [&](int kc, int s) {
        float* A = sA + s * A_STG;
        float* W = sW + s * W_STG;
#pragma unroll
        for (int i = 0; i < 4; i++) {
            int lin = tid + i * 256;
            int r   = lin >> 3;
            int c4  = (lin & 7) << 2;
            cp16(&A[r * SSTRIDE + c4], in + (size_t)(m0 + r) * DI + kc + c4);
        }
#pragma unroll
        for (int i = 0; i < 4; i++) {
            int lin = tid + i * 256;
            int w   = lin >> 9;          // 0: Wx, 1: Wf
            int rem = lin & 511;
            int r   = rem >> 3;
            int c4  = (rem & 7) << 2;
            const float* Wp = w ? Wf : Wx;
            cp16(&W[w * (64 * SSTRIDE) + r * SSTRIDE + c4],
                 Wp + (size_t)(o0 + r) * DI + kc + c4);
        }
        CP_COMMIT();
    };

    issue(0, 0);

    const int NCHK = DI / KC;   // 8
#pragma unroll 1
    for (int i = 0; i < NCHK; i++) {
        if (i < NCHK - 1) issue((i + 1) * KC, (i + 1) & 1);
        if (i < NCHK - 1) { CP_WAIT(1); } else { CP_WAIT(0); }
        __syncthreads();

        const float* A  = sA + (i & 1) * A_STG;
        const float* W0 = sW + (i & 1) * W_STG;
        const float* W1 = W0 + 64 * SSTRIDE;

#pragma unroll
        for (int ks = 0; ks < 4; ks++) {
            const int kk = ks * 8;
            uint32_t a[2][4];
#pragma unroll
            for (int mf = 0; mf < 2; mf++) {
                int rbase = (warpM * 32 + mf * 16 + gid) * SSTRIDE + kk + tig;
                a[mf][0] = f2tf32(A[rbase]);
                a[mf][1] = f2tf32(A[rbase + 8 * SSTRIDE]);
                a[mf][2] = f2tf32(A[rbase + 4]);
                a[mf][3] = f2tf32(A[rbase + 8 * SSTRIDE + 4]);
            }
#pragma unroll
            for (int nf = 0; nf < 4; nf++) {
                int ob = (warpN * 32 + nf * 8 + gid) * SSTRIDE + kk + tig;
                uint32_t wx0 = f2tf32(W0[ob]), wx1 = f2tf32(W0[ob + 4]);
                uint32_t wf0 = f2tf32(W1[ob]), wf1 = f2tf32(W1[ob + 4]);
#pragma unroll
                for (int mf = 0; mf < 2; mf++) {
                    MMA_TF32(accx[mf][nf], a[mf], wx0, wx1);
                    MMA_TF32(accf[mf][nf], a[mf], wf0, wf1);
                }
            }
        }
        __syncthreads();
    }

    // Epilogue: x = tanh(zx + bx), f = sigmoid(zf + bf + mask*1e4)
    // store (a,b) = (1-f, f*x) interleaved; pack 2 adjacent cols -> float4 STG.128
#pragma unroll
    for (int mf = 0; mf < 2; mf++) {
#pragma unroll
        for (int rr = 0; rr < 2; rr++) {
            int m = m0 + warpM * 32 + mf * 16 + rr * 8 + gid;
            float mk = mask[m] * 10000.0f;
#pragma unroll
            for (int nf = 0; nf < 4; nf++) {
                int o = o0 + warpN * 32 + nf * 8 + 2 * tig;
                float zx0 = accx[mf][nf][rr * 2 + 0] + bx[o];
                float zx1 = accx[mf][nf][rr * 2 + 1] + bx[o + 1];
                float zf0 = accf[mf][nf][rr * 2 + 0] + bf[o] + mk;
                float zf1 = accf[mf][nf][rr * 2 + 1] + bf[o + 1] + mk;
                float x0 = __fdividef(2.0f, 1.0f + __expf(-2.0f * zx0)) - 1.0f;
                float x1 = __fdividef(2.0f, 1.0f + __expf(-2.0f * zx1)) - 1.0f;
                float f0 = __fdividef(1.0f, 1.0f + __expf(-zf0));
                float f1 = __fdividef(1.0f, 1.0f + __expf(-zf1));
                float4 st;
                st.x = 1.0f - f0; st.y = f0 * x0;
                st.z = 1.0f - f1; st.w = f1 * x1;
                *(float4*)(&g_ab[((size_t)m * DO + o) * 2]) = st;
            }
        }
    }
}

// ---------------- Chunk-parallel linear-recurrence scan ----------------
// Phase 1: per-(b, chunk, o) composition (A = prod a, S = local scan from 0).
// Grid (B_, NCH) x 256 threads.
__global__ __launch_bounds__(256) void scan_carry()
{
    const int b = blockIdx.x;
    const int c = blockIdx.y;
    const int o = threadIdx.x;

    const float2* __restrict__ ab =
        (const float2*)g_ab + ((size_t)b * T_ + (size_t)c * CHUNK) * DO + o;

    float A = 1.0f, S = 0.0f;
#pragma unroll 8
    for (int t = 0; t < CHUNK; t++) {
        float2 v = ab[(size_t)t * DO];
        S = fmaf(v.x, S, v.y);
        A = A * v.x;
    }
    const int idx = (b * NCH + c) * DO + o;
    g_cA[idx] = A;
    g_cS[idx] = S;
}

// Phase 2: per-chain serial combine over NCH chunk carries.
__global__ __launch_bounds__(256) void scan_combine()
{
    const int b = blockIdx.x;
    const int o = threadIdx.x;

    float h = 0.0f;
#pragma unroll
    for (int c = 0; c < NCH; c++) {
        const int idx = (b * NCH + c) * DO + o;
        g_hin[idx] = h;
        h = fmaf(g_cA[idx], h, g_cS[idx]);
    }
}

// Phase 3: re-scan each chunk from its exact entry state, writing output.
__global__ __launch_bounds__(256) void scan_apply(float* __restrict__ out)
{
    const int b = blockIdx.x;
    const int c = blockIdx.y;
    const int o = threadIdx.x;

    const size_t base = ((size_t)b * T_ + (size_t)c * CHUNK) * DO + o;
    const float2* __restrict__ ab = (const float2*)g_ab + base;
    float* __restrict__ op = out + base;

    float h = g_hin[(b * NCH + c) * DO + o];
#pragma unroll 8
    for (int t = 0; t < CHUNK; t++) {
        float2 v = ab[(size_t)t * DO];
        h = fmaf(v.x, h, v.y);
        op[(size_t)t * DO] = h;
    }
}

extern "C" void kernel_launch(void* const* d_in, const int* in_sizes, int n_in,
                              void* d_out, int out_size)
{
    const float* in   = (const float*)d_in[0];
    const float* mask = (const float*)d_in[1];
    const float* Wx   = (const float*)d_in[2];
    const float* bx   = (const float*)d_in[3];
    const float* Wf   = (const float*)d_in[4];
    const float* bf   = (const float*)d_in[5];
    float* out = (float*)d_out;

    static bool attr_set = false;
    if (!attr_set) {
        cudaFuncSetAttribute(qrnn_gemm,
                             cudaFuncAttributeMaxDynamicSharedMemorySize,
                             SMEM_FLOATS * (int)sizeof(float));
        attr_set = true;
    }

    dim3 ggrid(DO / 64, M_TOTAL / 128);   // (4, 256)
    qrnn_gemm<<<ggrid, 256, SMEM_FLOATS * sizeof(float)>>>(in, mask, Wx, bx, Wf, bf);

    dim3 sgrid(B_, NCH);                  // (8, 64)
    scan_carry<<<sgrid, 256>>>();
    scan_combine<<<B_, 256>>>();
    scan_apply<<<sgrid, 256>>>(out);
}

// round 9
// speedup vs baseline: 1.3768x; 1.3768x over previous
#include <cuda_runtime.h>
#include <cstdint>

#define B_  8
#define T_  4096
#define DI  256
#define DO  256
#define M_TOTAL (B_ * T_)      // 32768

#define NCH   64               // half-chunks per sequence (apply granularity)
#define CHUNK (T_ / NCH)       // 64 steps per apply chunk
#define MTILE 128              // GEMM m-tile = one 128-step carry chunk

// Scratch: interleaved (a, b) = (1-f, f*x) pairs, [M_TOTAL][DO] float2 = 64 MB
__device__ float g_ab[(size_t)M_TOTAL * DO * 2];
// Per-(b, half-chunk, o) carry composition and resolved chunk-entry state
__device__ float g_cA[B_ * NCH * DO];
__device__ float g_cS[B_ * NCH * DO];
__device__ float g_hin[B_ * NCH * DO];

__device__ __forceinline__ uint32_t f2tf32(float x) {
    uint32_t r;
    asm("cvt.rna.tf32.f32 %0, %1;" : "=r"(r) : "f"(x));
    return r;
}

#define KC        32
#define SSTRIDE   36   // 32 + 4 pad: bank = 4*(lane/4)+lane%4 -> conflict-free
#define A_STG     (128 * SSTRIDE)       // uint32 per A stage
#define W_STG     (2 * 64 * SSTRIDE)    // uint32 per W stage (both matrices)
#define SMEM_WORDS (2 * (A_STG + W_STG))   // 18432 words = 72 KB (also holds sAB 64 KB)

#define MMA_TF32(d, a, b0, b1)                                            \
    asm volatile(                                                         \
        "mma.sync.aligned.m16n8k8.row.col.f32.tf32.tf32.f32 "            \
        "{%0,%1,%2,%3}, {%4,%5,%6,%7}, {%8,%9}, {%0,%1,%2,%3};"          \
        : "+f"((d)[0]), "+f"((d)[1]), "+f"((d)[2]), "+f"((d)[3])          \
        : "r"((a)[0]), "r"((a)[1]), "r"((a)[2]), "r"((a)[3]),             \
          "r"(b0), "r"(b1))

// CTA: 256 threads, tile M=128 x O=64, both projections + fused chunk-carry.
// Grid: (DO/64, M_TOTAL/128) = (4, 256). Register-prefetch K pipeline.
__global__ __launch_bounds__(256, 2) void qrnn_gemm(
    const float* __restrict__ in,    // [M_TOTAL, DI]
    const float* __restrict__ mask,  // [M_TOTAL]
    const float* __restrict__ Wx,    // [DO, DI]
    const float* __restrict__ bx,    // [DO]
    const float* __restrict__ Wf,    // [DO, DI]
    const float* __restrict__ bf)    // [DO]
{
    extern __shared__ uint32_t smem[];
    uint32_t* sA = smem;                 // [2][128*SSTRIDE]
    uint32_t* sW = smem + 2 * A_STG;     // [2][2][64*SSTRIDE]
    __shared__ float2 sSeg[4][64];       // per-segment (A, S) partials

    const int tid   = threadIdx.x;
    const int lane  = tid & 31;
    const int warp  = tid >> 5;
    const int warpM = warp & 3;      // 4 warps along M (32 rows each)
    const int warpN = warp >> 2;     // 2 warps along O (32 cols each)
    const int gid   = lane >> 2;     // 0..7
    const int tig   = lane & 3;      // 0..3

    const int m0 = blockIdx.y * MTILE;
    const int o0 = blockIdx.x * 64;

    float accx[2][4][4];
    float accf[2][4][4];
#pragma unroll
    for (int mf = 0; mf < 2; mf++)
#pragma unroll
        for (int nf = 0; nf < 4; nf++)
#pragma unroll
            for (int c = 0; c < 4; c++) { accx[mf][nf][c] = 0.f; accf[mf][nf][c] = 0.f; }

    // Per-thread staging coords (fixed): 4 A rows, 4 W rows
    float4 pa[4], pw[4];
    int arow[4], acol;
    int wrow[4], wsel[4], wcol[4];
#pragma unroll
    for (int i = 0; i < 4; i++) {
        int lin = tid + i * 256;
        arow[i] = lin >> 3;
        int wl  = lin >> 9;          // 0: Wx, 1: Wf
        int rem = lin & 511;
        wsel[i] = wl;
        wrow[i] = rem >> 3;
        wcol[i] = (rem & 7) << 2;
    }
    acol = (tid & 7) << 2;

    auto ldg_issue = [&](int kc) {
#pragma unroll
        for (int i = 0; i < 4; i++)
            pa[i] = *(const float4*)(in + (size_t)(m0 + arow[i]) * DI + kc + acol);
#pragma unroll
        for (int i = 0; i < 4; i++) {
            const float* Wp = wsel[i] ? Wf : Wx;
            pw[i] = *(const float4*)(Wp + (size_t)(o0 + wrow[i]) * DI + kc + wcol[i]);
        }
    };
    auto sts = [&](int s) {
        uint32_t* A = sA + s * A_STG;
        uint32_t* W = sW + s * W_STG;
#pragma unroll
        for (int i = 0; i < 4; i++) {
            uint32_t* d = &A[arow[i] * SSTRIDE + acol];
            d[0] = f2tf32(pa[i].x); d[1] = f2tf32(pa[i].y);
            d[2] = f2tf32(pa[i].z); d[3] = f2tf32(pa[i].w);
        }
#pragma unroll
        for (int i = 0; i < 4; i++) {
            uint32_t* d = &W[wsel[i] * (64 * SSTRIDE) + wrow[i] * SSTRIDE + wcol[i]];
            d[0] = f2tf32(pw[i].x); d[1] = f2tf32(pw[i].y);
            d[2] = f2tf32(pw[i].z); d[3] = f2tf32(pw[i].w);
        }
    };

    ldg_issue(0);
    sts(0);
    __syncthreads();

    const int NCHK = DI / KC;   // 8
#pragma unroll 1
    for (int i = 0; i < NCHK; i++) {
        if (i < NCHK - 1) ldg_issue((i + 1) * KC);   // overlap with MMAs below

        const uint32_t* A  = sA + (i & 1) * A_STG;
        const uint32_t* W0 = sW + (i & 1) * W_STG;
        const uint32_t* W1 = W0 + 64 * SSTRIDE;

#pragma unroll
        for (int ks = 0; ks < 4; ks++) {
            const int kk = ks * 8;
            uint32_t a[2][4];
#pragma unroll
            for (int mf = 0; mf < 2; mf++) {
                int rbase = (warpM * 32 + mf * 16 + gid) * SSTRIDE + kk + tig;
                a[mf][0] = A[rbase];
                a[mf][1] = A[rbase + 8 * SSTRIDE];
                a[mf][2] = A[rbase + 4];
                a[mf][3] = A[rbase + 8 * SSTRIDE + 4];
            }
#pragma unroll
            for (int nf = 0; nf < 4; nf++) {
                int ob = (warpN * 32 + nf * 8 + gid) * SSTRIDE + kk + tig;
                uint32_t wx0 = W0[ob], wx1 = W0[ob + 4];
                uint32_t wf0 = W1[ob], wf1 = W1[ob + 4];
#pragma unroll
                for (int mf = 0; mf < 2; mf++) {
                    MMA_TF32(accx[mf][nf], a[mf], wx0, wx1);
                    MMA_TF32(accf[mf][nf], a[mf], wf0, wf1);
                }
            }
        }
        __syncthreads();              // all reads of stage i&1 done
        if (i < NCHK - 1) {
            sts((i + 1) & 1);
            __syncthreads();          // stage (i+1)&1 ready
        }
    }

    // ---- Epilogue: activations, write (a,b) to gmem AND smem for carry ----
    float2* sAB = (float2*)smem;       // [128 rows][64 o-cols], 64 KB (reuses stages)

#pragma unroll
    for (int mf = 0; mf < 2; mf++) {
#pragma unroll
        for (int rr = 0; rr < 2; rr++) {
            int rloc = warpM * 32 + mf * 16 + rr * 8 + gid;
            int m = m0 + rloc;
            float mk = mask[m] * 10000.0f;
#pragma unroll
            for (int nf = 0; nf < 4; nf++) {
                int oloc = warpN * 32 + nf * 8 + 2 * tig;
                int o = o0 + oloc;
                float zx0 = accx[mf][nf][rr * 2 + 0] + bx[o];
                float zx1 = accx[mf][nf][rr * 2 + 1] + bx[o + 1];
                float zf0 = accf[mf][nf][rr * 2 + 0] + bf[o] + mk;
                float zf1 = accf[mf][nf][rr * 2 + 1] + bf[o + 1] + mk;
                float x0 = __fdividef(2.0f, 1.0f + __expf(-2.0f * zx0)) - 1.0f;
                float x1 = __fdividef(2.0f, 1.0f + __expf(-2.0f * zx1)) - 1.0f;
                float f0 = __fdividef(1.0f, 1.0f + __expf(-zf0));
                float f1 = __fdividef(1.0f, 1.0f + __expf(-zf1));
                float4 st;
                st.x = 1.0f - f0; st.y = f0 * x0;
                st.z = 1.0f - f1; st.w = f1 * x1;
                *(float4*)(&g_ab[((size_t)m * DO + o) * 2]) = st;
                *(float4*)(&sAB[rloc * 64 + oloc]) = st;
            }
        }
    }
    __syncthreads();

    // ---- Fused carry: 4 segments of 32 rows, combine to 2 half-chunk carries ----
    {
        const int o   = tid & 63;
        const int seg = tid >> 6;          // 0..3
        const float2* col = sAB + seg * 32 * 64 + o;
        float A = 1.0f, S = 0.0f;
#pragma unroll 8
        for (int r = 0; r < 32; r++) {
            float2 v = col[r * 64];
            S = fmaf(v.x, S, v.y);
            A = A * v.x;
        }
        sSeg[seg][o] = make_float2(A, S);
    }
    __syncthreads();

    if (tid < 128) {
        const int o    = tid & 63;
        const int half = tid >> 6;         // 0..1
        float2 s0 = sSeg[2 * half][o];
        float2 s1 = sSeg[2 * half + 1][o];
        float A = s1.x * s0.x;
        float S = fmaf(s1.x, s0.y, s1.y);
        const int b = blockIdx.y >> 5;           // 32 m-tiles per sequence
        const int c = blockIdx.y & 31;           // 128-row chunk within sequence
        const int idx = (b * NCH + c * 2 + half) * DO + o0 + o;
        g_cA[idx] = A;
        g_cS[idx] = S;
    }
}

// Phase 2: per-chain serial combine over NCH half-chunk carries.
__global__ __launch_bounds__(256) void scan_combine()
{
    const int b = blockIdx.x;
    const int o = threadIdx.x;

    float h = 0.0f;
#pragma unroll
    for (int c = 0; c < NCH; c++) {
        const int idx = (b * NCH + c) * DO + o;
        g_hin[idx] = h;
        h = fmaf(g_cA[idx], h, g_cS[idx]);
    }
}

// Phase 3: re-scan each half-chunk from its exact entry state, writing output.
// One thread handles TWO adjacent chains: LDG.128 + STG.64 per step.
__global__ __launch_bounds__(128) void scan_apply(float* __restrict__ out)
{
    const int b = blockIdx.x;
    const int c = blockIdx.y;
    const int j = threadIdx.x;            // 0..127 -> chains 2j, 2j+1

    const size_t rowbase = ((size_t)b * T_ + (size_t)c * CHUNK) * DO;
    const float4* __restrict__ ab = (const float4*)(g_ab + (rowbase + 2 * j) * 2);
    float2* __restrict__ op = (float2*)(out + rowbase) + j;

    const int hidx = (b * NCH + c) * DO + 2 * j;
    float h0 = g_hin[hidx];
    float h1 = g_hin[hidx + 1];

#pragma unroll 8
    for (int t = 0; t < CHUNK; t++) {
        float4 v = ab[(size_t)t * (DO / 2)];   // (a0,b0,a1,b1)
        h0 = fmaf(v.x, h0, v.y);
        h1 = fmaf(v.z, h1, v.w);
        op[(size_t)t * (DO / 2)] = make_float2(h0, h1);
    }
}

extern "C" void kernel_launch(void* const* d_in, const int* in_sizes, int n_in,
                              void* d_out, int out_size)
{
    const float* in   = (const float*)d_in[0];
    const float* mask = (const float*)d_in[1];
    const float* Wx   = (const float*)d_in[2];
    const float* bx   = (const float*)d_in[3];
    const float* Wf   = (const float*)d_in[4];
    const float* bf   = (const float*)d_in[5];
    float* out = (float*)d_out;

    static bool attr_set = false;
    if (!attr_set) {
        cudaFuncSetAttribute(qrnn_gemm,
                             cudaFuncAttributeMaxDynamicSharedMemorySize,
                             SMEM_WORDS * (int)sizeof(uint32_t));
        attr_set = true;
    }

    dim3 ggrid(DO / 64, M_TOTAL / MTILE);   // (4, 256)
    qrnn_gemm<<<ggrid, 256, SMEM_WORDS * sizeof(uint32_t)>>>(in, mask, Wx, bx, Wf, bf);

    scan_combine<<<B_, 256>>>();
    dim3 sgrid(B_, NCH);                    // (8, 64)
    scan_apply<<<sgrid, 128>>>(out);
}